// round 4
// baseline (speedup 1.0000x reference)
#include <cuda_runtime.h>
#include <cuda_bf16.h>
#include <cstdint>

#define H      128
#define NH     8
#define HDIM   16
#define MAXDEG 16
#define MAXN_PAD 50048      // 391 * 128, >= N

// ---------------- scratch (device globals: no allocations allowed) ----------
// Q, K stored PERMUTED: feature f = d*8+hd  ->  slot hd*16+d  (head-contiguous)
// V stored in original layout.
__device__ __align__(16) float g_Q[MAXN_PAD * H];
__device__ __align__(16) float g_K[MAXN_PAD * H];
__device__ __align__(16) float g_V[MAXN_PAD * H];

// ---------------- tf32 helpers ----------------------------------------------
__device__ __forceinline__ void split_tf32(float f, unsigned& hi, unsigned& lo) {
    unsigned h;
    asm("cvt.rna.tf32.f32 %0, %1;" : "=r"(h) : "f"(f));
    float l = f - __uint_as_float(h);
    unsigned lw;
    asm("cvt.rna.tf32.f32 %0, %1;" : "=r"(lw) : "f"(l));
    hi = h; lo = lw;
}

__device__ __forceinline__ void mma_tf32(float c[4], const unsigned a[4],
                                         unsigned b0, unsigned b1) {
    asm volatile(
        "mma.sync.aligned.m16n8k8.row.col.f32.tf32.tf32.f32 "
        "{%0,%1,%2,%3},{%4,%5,%6,%7},{%8,%9},{%0,%1,%2,%3};"
        : "+f"(c[0]), "+f"(c[1]), "+f"(c[2]), "+f"(c[3])
        : "r"(a[0]), "r"(a[1]), "r"(a[2]), "r"(a[3]), "r"(b0), "r"(b1));
}

// ---------------- QKV projection on tensor cores (3xTF32) -------------------
// C = h @ W^T + b  (x 0.25 for Q).  blockIdx.z: 0->Q, 1->K, 2->V.
// Block: 128 rows x 128 cols, 256 threads (8 warps), warp tile 32x64.
// Q and K written head-permuted for the attention kernel.
__global__ __launch_bounds__(256) void qkv_gemm_tc(
    const float* __restrict__ hmat,
    const float* __restrict__ Wq, const float* __restrict__ bq,
    const float* __restrict__ Wk, const float* __restrict__ bk,
    const float* __restrict__ Wv, const float* __restrict__ bv,
    int N)
{
    const int z = blockIdx.z;
    const float* __restrict__ W    = (z == 0) ? Wq : (z == 1) ? Wk : Wv;
    const float* __restrict__ bias = (z == 0) ? bq : (z == 1) ? bk : bv;
    float* __restrict__ C          = (z == 0) ? g_Q : (z == 1) ? g_K : g_V;
    const float scale   = (z == 0) ? 0.25f : 1.0f;   // head_dim^-0.5 = 16^-0.5
    const bool  permute = (z < 2);

    __shared__ __align__(16) float As[128][36];   // [m][k], pad 4 -> conflict-free
    __shared__ __align__(16) float Ws[128][36];   // [n][k]

    const int tid   = threadIdx.x;
    const int warp  = tid >> 5;
    const int lane  = tid & 31;
    const int group = lane >> 2;       // 0..7
    const int tg    = lane & 3;        // 0..3
    const int wm    = (warp & 3) * 32; // warp row offset within block tile
    const int wn    = (warp >> 2) * 64;// warp col offset
    const int row0  = blockIdx.x * 128;

    float acc[2][8][4];
#pragma unroll
    for (int mt = 0; mt < 2; mt++)
#pragma unroll
        for (int nt = 0; nt < 8; nt++)
#pragma unroll
            for (int j = 0; j < 4; j++) acc[mt][nt][j] = 0.0f;

    for (int kk = 0; kk < 128; kk += 32) {
        // stage A (h rows) and B (W rows) tiles: 128 x 32 each
#pragma unroll
        for (int i = 0; i < 4; i++) {
            int idx = tid + i * 256;
            int r  = idx >> 3;
            int c4 = (idx & 7) * 4;
            float4 a = make_float4(0.f, 0.f, 0.f, 0.f);
            if (row0 + r < N)
                a = *reinterpret_cast<const float4*>(hmat + (size_t)(row0 + r) * H + kk + c4);
            *reinterpret_cast<float4*>(&As[r][c4]) = a;
            float4 w = *reinterpret_cast<const float4*>(W + (size_t)r * H + kk + c4);
            *reinterpret_cast<float4*>(&Ws[r][c4]) = w;
        }
        __syncthreads();

#pragma unroll
        for (int ks = 0; ks < 4; ks++) {
            const int k0 = ks * 8;
            // A fragments for 2 m-tiles, split hi/lo
            unsigned ahi[2][4], alo[2][4];
#pragma unroll
            for (int mt = 0; mt < 2; mt++) {
                int r = wm + mt * 16 + group;
                split_tf32(As[r    ][k0 + tg    ], ahi[mt][0], alo[mt][0]);
                split_tf32(As[r + 8][k0 + tg    ], ahi[mt][1], alo[mt][1]);
                split_tf32(As[r    ][k0 + tg + 4], ahi[mt][2], alo[mt][2]);
                split_tf32(As[r + 8][k0 + tg + 4], ahi[mt][3], alo[mt][3]);
            }
#pragma unroll
            for (int nt = 0; nt < 8; nt++) {
                int n = wn + nt * 8 + group;
                unsigned bhi0, blo0, bhi1, blo1;
                split_tf32(Ws[n][k0 + tg    ], bhi0, blo0);
                split_tf32(Ws[n][k0 + tg + 4], bhi1, blo1);
#pragma unroll
                for (int mt = 0; mt < 2; mt++) {
                    mma_tf32(acc[mt][nt], ahi[mt], bhi0, bhi1);   // hi*hi
                    mma_tf32(acc[mt][nt], ahi[mt], blo0, blo1);   // hi*lo
                    mma_tf32(acc[mt][nt], alo[mt], bhi0, bhi1);   // lo*hi
                }
            }
        }
        __syncthreads();
    }

    // epilogue: bias + scale + (optional) head-permute store
#pragma unroll
    for (int nt = 0; nt < 8; nt++) {
        int c0 = wn + nt * 8 + 2 * tg;
        int c1 = c0 + 1;
        float b0 = __ldg(bias + c0);
        float b1 = __ldg(bias + c1);
        int p0 = permute ? ((c0 & 7) * HDIM + (c0 >> 3)) : c0;
        int p1 = permute ? ((c1 & 7) * HDIM + (c1 >> 3)) : c1;
#pragma unroll
        for (int mt = 0; mt < 2; mt++) {
            int r = row0 + wm + mt * 16 + group;
            if (r < N) {
                C[(size_t)r * H + p0] = (acc[mt][nt][0] + b0) * scale;
                C[(size_t)r * H + p1] = (acc[mt][nt][1] + b1) * scale;
            }
            if (r + 8 < N) {
                C[(size_t)(r + 8) * H + p0] = (acc[mt][nt][2] + b0) * scale;
                C[(size_t)(r + 8) * H + p1] = (acc[mt][nt][3] + b1) * scale;
            }
        }
    }
}

// ---------------- fused sparse attention: one warp per node -----------------
// Q,K permuted (head-contiguous): slot p = hd*16 + d.
// Lane holds float4 at p = 4*lane..4*lane+3 -> head = lane>>2 (scores),
// and in original layout f = 4*lane+j -> head = 4*(lane&1)+j (V pass).
__global__ __launch_bounds__(256) void attn_kernel2(
    const int* __restrict__ row_ptr,
    const int* __restrict__ col_ind,
    float* __restrict__ out,
    int N)
{
    __shared__ float att[8][NH][MAXDEG];   // [local warp][head][edge]

    const int wl   = threadIdx.x >> 5;
    const int lane = threadIdx.x & 31;
    const int node = blockIdx.x * 8 + wl;
    if (node >= N) return;                 // warp-uniform; only __syncwarp below

    const int start = row_ptr[node];
    int deg = row_ptr[node + 1] - start;
    if (deg > MAXDEG) deg = MAXDEG;

    int colv = 0;
    if (lane < MAXDEG && lane < deg) colv = col_ind[start + lane];

    const float4 q4 = *reinterpret_cast<const float4*>(g_Q + (size_t)node * H + lane * 4);

    const float NEG_INF = __int_as_float(0xff800000);
    float sc[MAXDEG];
#pragma unroll
    for (int e = 0; e < MAXDEG; e++) {
        int col = __shfl_sync(0xffffffffu, colv, e);
        float4 k4 = __ldg(reinterpret_cast<const float4*>(g_K + (size_t)col * H) + lane);
        float p = q4.x * k4.x + q4.y * k4.y + q4.z * k4.z + q4.w * k4.w;
        p += __shfl_xor_sync(0xffffffffu, p, 1);
        p += __shfl_xor_sync(0xffffffffu, p, 2);   // quad = 16 d's of head lane>>2
        sc[e] = (e < deg) ? p : NEG_INF;
    }

    // per-lane softmax over edges (all 4 lanes of a quad hold identical copies)
    float m = NEG_INF;
#pragma unroll
    for (int e = 0; e < MAXDEG; e++) m = fmaxf(m, sc[e]);
    float s = 0.0f;
#pragma unroll
    for (int e = 0; e < MAXDEG; e++) { float x = __expf(sc[e] - m); sc[e] = x; s += x; }
    float r = __frcp_rn(s);
#pragma unroll
    for (int e = 0; e < MAXDEG; e++) sc[e] *= r;

    // transpose attn to smem: lane (hd = lane>>2) stores edges e0..e0+3
    {
        int hd = lane >> 2;
        int e0 = (lane & 3) * 4;
        *reinterpret_cast<float4*>(&att[wl][hd][e0]) =
            make_float4(sc[e0], sc[e0 + 1], sc[e0 + 2], sc[e0 + 3]);
    }
    __syncwarp();

    // bspmm: coalesced V rows, feature f = 4*lane+j -> head 4*(lane&1)+j
    const int base = (lane & 1) * 4;
    float4 acc = make_float4(0.f, 0.f, 0.f, 0.f);
#pragma unroll
    for (int e = 0; e < MAXDEG; e++) {
        int col = __shfl_sync(0xffffffffu, colv, e);
        float4 v4 = __ldg(reinterpret_cast<const float4*>(g_V + (size_t)col * H) + lane);
        acc.x += att[wl][base + 0][e] * v4.x;
        acc.y += att[wl][base + 1][e] * v4.y;
        acc.z += att[wl][base + 2][e] * v4.z;
        acc.w += att[wl][base + 3][e] * v4.w;
    }
    *reinterpret_cast<float4*>(out + (size_t)node * H + lane * 4) = acc;
}

// ---------------- launch -----------------------------------------------------
extern "C" void kernel_launch(void* const* d_in, const int* in_sizes, int n_in,
                              void* d_out, int out_size) {
    const float* h   = (const float*)d_in[0];
    const float* Wq  = (const float*)d_in[1];
    const float* bq  = (const float*)d_in[2];
    const float* Wk  = (const float*)d_in[3];
    const float* bk  = (const float*)d_in[4];
    const float* Wv  = (const float*)d_in[5];
    const float* bv  = (const float*)d_in[6];
    const int* row_ptr = (const int*)d_in[7];
    const int* col_ind = (const int*)d_in[8];
    float* out = (float*)d_out;

    const int N = in_sizes[0] / H;

    dim3 ggrid((N + 127) / 128, 1, 3);
    qkv_gemm_tc<<<ggrid, 256>>>(h, Wq, bq, Wk, bk, Wv, bv, N);

    const int ablocks = (N + 7) / 8;       // 8 nodes (warps) per 256-thread block
    attn_kernel2<<<ablocks, 256>>>(row_ptr, col_ind, out, N);
}

// round 6
// speedup vs baseline: 1.7900x; 1.7900x over previous
#include <cuda_runtime.h>
#include <cuda_bf16.h>
#include <cstdint>

#define H      128
#define NH     8
#define HDIM   16
#define MAXDEG 16
#define MAXN_PAD 50048      // 391 * 128, >= N

// ---------------- scratch (device globals: no allocations allowed) ----------
// Q, K stored PERMUTED: feature f = d*8+hd  ->  slot hd*16+d  (head-contiguous)
// V stored in original layout.
__device__ __align__(16) float g_Q[MAXN_PAD * H];
__device__ __align__(16) float g_K[MAXN_PAD * H];
__device__ __align__(16) float g_V[MAXN_PAD * H];

// ---------------- packed f32x2 helpers --------------------------------------
__device__ __forceinline__ unsigned long long fma2(unsigned long long a,
                                                   unsigned long long b,
                                                   unsigned long long c) {
    unsigned long long d;
    asm("fma.rn.f32x2 %0, %1, %2, %3;" : "=l"(d) : "l"(a), "l"(b), "l"(c));
    return d;
}
__device__ __forceinline__ unsigned long long dup2(float x) {
    unsigned long long r;
    unsigned int xi = __float_as_uint(x);
    asm("mov.b64 %0, {%1, %1};" : "=l"(r) : "r"(xi));
    return r;
}
__device__ __forceinline__ void unpack2(unsigned long long v, float& lo, float& hi) {
    unsigned int a, b;
    asm("mov.b64 {%0, %1}, %2;" : "=r"(a), "=r"(b) : "l"(v));
    lo = __uint_as_float(a);
    hi = __uint_as_float(b);
}

// ---------------- QKV projection: C = h @ W^T + b (x scale for Q) -----------
// blockIdx.z: 0 -> Q (scale 0.25, permuted), 1 -> K (permuted), 2 -> V.
// 128x128 output tile per block, BK=32, 256 threads, 8x8 microtile, f32x2 FMA.
// Software-pipelined: prefetch next k-chunk to registers during compute.
__global__ __launch_bounds__(256, 2) void qkv_gemm(
    const float* __restrict__ hmat,
    const float* __restrict__ Wq, const float* __restrict__ bq,
    const float* __restrict__ Wk, const float* __restrict__ bk,
    const float* __restrict__ Wv, const float* __restrict__ bv,
    int N)
{
    const int z = blockIdx.z;
    const float* __restrict__ W    = (z == 0) ? Wq : (z == 1) ? Wk : Wv;
    const float* __restrict__ bias = (z == 0) ? bq : (z == 1) ? bk : bv;
    float* __restrict__ C          = (z == 0) ? g_Q : (z == 1) ? g_K : g_V;
    const float scale   = (z == 0) ? 0.25f : 1.0f;   // head_dim^-0.5 = 16^-0.5
    const bool  permute = (z < 2);

    __shared__ __align__(16) float As[32][132];    // [k][m], pitch 132 (16B-aligned rows)
    __shared__ __align__(16) float Bs[32][132];    // [k][n]

    const int tid  = threadIdx.x;
    const int row0 = blockIdx.x * 128;
    const int sr   = tid >> 1;               // staging row 0..127
    const int sc   = (tid & 1) * 16;         // staging col base 0 or 16
    const int tx   = tid & 15;               // n-tile 0..15
    const int ty   = tid >> 4;               // m-tile 0..15
    const bool arow_ok = (row0 + sr < N);

    unsigned long long acc[8][4];
#pragma unroll
    for (int i = 0; i < 8; i++)
#pragma unroll
        for (int j = 0; j < 4; j++) acc[i][j] = 0ULL;

    // prefetch chunk 0
    float4 av[4], wv[4];
#pragma unroll
    for (int i = 0; i < 4; i++) {
        av[i] = arow_ok
            ? *reinterpret_cast<const float4*>(hmat + (size_t)(row0 + sr) * H + sc + i * 4)
            : make_float4(0.f, 0.f, 0.f, 0.f);
        wv[i] = *reinterpret_cast<const float4*>(W + (size_t)sr * H + sc + i * 4);
    }

    for (int chunk = 0; chunk < 4; chunk++) {
        // store staged regs to smem (transposed)
#pragma unroll
        for (int i = 0; i < 4; i++) {
            int k0 = sc + i * 4;
            As[k0 + 0][sr] = av[i].x; As[k0 + 1][sr] = av[i].y;
            As[k0 + 2][sr] = av[i].z; As[k0 + 3][sr] = av[i].w;
            Bs[k0 + 0][sr] = wv[i].x; Bs[k0 + 1][sr] = wv[i].y;
            Bs[k0 + 2][sr] = wv[i].z; Bs[k0 + 3][sr] = wv[i].w;
        }
        __syncthreads();

        // prefetch next chunk while computing this one
        if (chunk < 3) {
            int kk = (chunk + 1) * 32;
#pragma unroll
            for (int i = 0; i < 4; i++) {
                av[i] = arow_ok
                    ? *reinterpret_cast<const float4*>(hmat + (size_t)(row0 + sr) * H + kk + sc + i * 4)
                    : make_float4(0.f, 0.f, 0.f, 0.f);
                wv[i] = *reinterpret_cast<const float4*>(W + (size_t)sr * H + kk + sc + i * 4);
            }
        }

#pragma unroll 8
        for (int k = 0; k < 32; k++) {
            ulonglong2 b01 = *reinterpret_cast<const ulonglong2*>(&Bs[k][tx * 8]);
            ulonglong2 b23 = *reinterpret_cast<const ulonglong2*>(&Bs[k][tx * 8 + 4]);
            float4 a0 = *reinterpret_cast<const float4*>(&As[k][ty * 8]);
            float4 a1 = *reinterpret_cast<const float4*>(&As[k][ty * 8 + 4]);
            unsigned long long ad[8];
            ad[0] = dup2(a0.x); ad[1] = dup2(a0.y); ad[2] = dup2(a0.z); ad[3] = dup2(a0.w);
            ad[4] = dup2(a1.x); ad[5] = dup2(a1.y); ad[6] = dup2(a1.z); ad[7] = dup2(a1.w);
#pragma unroll
            for (int i = 0; i < 8; i++) {
                acc[i][0] = fma2(ad[i], b01.x, acc[i][0]);
                acc[i][1] = fma2(ad[i], b01.y, acc[i][1]);
                acc[i][2] = fma2(ad[i], b23.x, acc[i][2]);
                acc[i][3] = fma2(ad[i], b23.y, acc[i][3]);
            }
        }
        __syncthreads();
    }

    // epilogue: bias + scale + (optional) head-permute store
    // thread cols c = tx*8 + u (u=0..7), rows r = ty*8 + i
    float bl[8];
#pragma unroll
    for (int u = 0; u < 8; u++) bl[u] = __ldg(bias + tx * 8 + u);

#pragma unroll
    for (int i = 0; i < 8; i++) {
        int gr = row0 + ty * 8 + i;
        if (gr >= N) continue;
        float vals[8];
#pragma unroll
        for (int j = 0; j < 4; j++) {
            float lo, hi;
            unpack2(acc[i][j], lo, hi);
            vals[2 * j]     = (lo + bl[2 * j])     * scale;
            vals[2 * j + 1] = (hi + bl[2 * j + 1]) * scale;
        }
        float* crow = C + (size_t)gr * H;
        if (permute) {
            // c = tx*8+u -> slot (c&7)*16 + (c>>3) = u*16 + tx
#pragma unroll
            for (int u = 0; u < 8; u++) crow[u * 16 + tx] = vals[u];
        } else {
            *reinterpret_cast<float4*>(crow + tx * 8) =
                make_float4(vals[0], vals[1], vals[2], vals[3]);
            *reinterpret_cast<float4*>(crow + tx * 8 + 4) =
                make_float4(vals[4], vals[5], vals[6], vals[7]);
        }
    }
}

// ---------------- fused sparse attention: one warp per node -----------------
// Q,K permuted (head-contiguous): slot p = hd*16 + d.
// Lane holds float4 at p = 4*lane..4*lane+3 -> head = lane>>2 (scores),
// and in original layout f = 4*lane+j -> head = 4*(lane&1)+j (V pass).
__global__ __launch_bounds__(256) void attn_kernel2(
    const int* __restrict__ row_ptr,
    const int* __restrict__ col_ind,
    float* __restrict__ out,
    int N)
{
    __shared__ float att[8][NH][MAXDEG];   // [local warp][head][edge]

    const int wl   = threadIdx.x >> 5;
    const int lane = threadIdx.x & 31;
    const int node = blockIdx.x * 8 + wl;
    if (node >= N) return;                 // warp-uniform; only __syncwarp below

    const int start = row_ptr[node];
    int deg = row_ptr[node + 1] - start;
    if (deg > MAXDEG) deg = MAXDEG;

    int colv = 0;
    if (lane < MAXDEG && lane < deg) colv = col_ind[start + lane];

    const float4 q4 = *reinterpret_cast<const float4*>(g_Q + (size_t)node * H + lane * 4);

    const float NEG_INF = __int_as_float(0xff800000);
    float sc[MAXDEG];
#pragma unroll
    for (int e = 0; e < MAXDEG; e++) {
        int col = __shfl_sync(0xffffffffu, colv, e);
        float4 k4 = __ldg(reinterpret_cast<const float4*>(g_K + (size_t)col * H) + lane);
        float p = q4.x * k4.x + q4.y * k4.y + q4.z * k4.z + q4.w * k4.w;
        p += __shfl_xor_sync(0xffffffffu, p, 1);
        p += __shfl_xor_sync(0xffffffffu, p, 2);   // quad = 16 d's of head lane>>2
        sc[e] = (e < deg) ? p : NEG_INF;
    }

    // per-lane softmax over edges (all 4 lanes of a quad hold identical copies)
    float m = NEG_INF;
#pragma unroll
    for (int e = 0; e < MAXDEG; e++) m = fmaxf(m, sc[e]);
    float s = 0.0f;
#pragma unroll
    for (int e = 0; e < MAXDEG; e++) { float x = __expf(sc[e] - m); sc[e] = x; s += x; }
    float r = __frcp_rn(s);
#pragma unroll
    for (int e = 0; e < MAXDEG; e++) sc[e] *= r;

    // transpose attn to smem: lane (hd = lane>>2) stores edges e0..e0+3
    {
        int hd = lane >> 2;
        int e0 = (lane & 3) * 4;
        *reinterpret_cast<float4*>(&att[wl][hd][e0]) =
            make_float4(sc[e0], sc[e0 + 1], sc[e0 + 2], sc[e0 + 3]);
    }
    __syncwarp();

    // bspmm: coalesced V rows, feature f = 4*lane+j -> head 4*(lane&1)+j
    const int base = (lane & 1) * 4;
    float4 acc = make_float4(0.f, 0.f, 0.f, 0.f);
#pragma unroll
    for (int e = 0; e < MAXDEG; e++) {
        int col = __shfl_sync(0xffffffffu, colv, e);
        float4 v4 = __ldg(reinterpret_cast<const float4*>(g_V + (size_t)col * H) + lane);
        acc.x += att[wl][base + 0][e] * v4.x;
        acc.y += att[wl][base + 1][e] * v4.y;
        acc.z += att[wl][base + 2][e] * v4.z;
        acc.w += att[wl][base + 3][e] * v4.w;
    }
    *reinterpret_cast<float4*>(out + (size_t)node * H + lane * 4) = acc;
}

// ---------------- launch -----------------------------------------------------
extern "C" void kernel_launch(void* const* d_in, const int* in_sizes, int n_in,
                              void* d_out, int out_size) {
    const float* h   = (const float*)d_in[0];
    const float* Wq  = (const float*)d_in[1];
    const float* bq  = (const float*)d_in[2];
    const float* Wk  = (const float*)d_in[3];
    const float* bk  = (const float*)d_in[4];
    const float* Wv  = (const float*)d_in[5];
    const float* bv  = (const float*)d_in[6];
    const int* row_ptr = (const int*)d_in[7];
    const int* col_ind = (const int*)d_in[8];
    float* out = (float*)d_out;

    const int N = in_sizes[0] / H;

    dim3 ggrid((N + 127) / 128, 1, 3);
    qkv_gemm<<<ggrid, 256>>>(h, Wq, bq, Wk, bk, Wv, bv, N);

    const int ablocks = (N + 7) / 8;       // 8 nodes (warps) per 256-thread block
    attn_kernel2<<<ablocks, 256>>>(row_ptr, col_ind, out, N);
}